// round 5
// baseline (speedup 1.0000x reference)
#include <cuda_runtime.h>

// HiPPO-LegS scan:  x_t = A_t x_{t-1} + inputs[t,b] * B_t,  x_{-1} = 0
//   inputs    : (L, 32)      float32
//   A_stacked : (L, 128,128) float32
//   B_stacked : (L, 128)     float32
//   out       : (L, 32, 128) float32
//
// Chunked parallel scan, C = 16 steps per chunk, K = L/C chunks:
//   Pass 1: per chunk compute [M_k | v_k] via augmented chain (parallel over chunks)
//   Pass 2: sequential scan over K chunk transitions (parallel over batch cols)
//   Pass 3: local re-scan from correct chunk-start state, write outputs

#define NDIM 128
#define BDIM 32
#define CSZ  16
#define KMAX 64
#define APAD 132   // padded A-tile row stride (floats) — kills bank conflicts, keeps 16B align

// scratch (allowed: __device__ globals)
__device__ float g_Mt[KMAX * NDIM * NDIM];  // [k][j][i] = M_k[i][j]  (transposed)
__device__ float g_v [KMAX * BDIM * NDIM];  // [k][b][i] chunk-local final state (zero init)
__device__ float g_S [KMAX * BDIM * NDIM];  // [k][b][i] state BEFORE chunk k

// ---------------------------------------------------------------------------
// Pass 1: chunk reduction. Augmented state W = [P (128 cols) | Y (32 cols)],
// 160 columns split into 2 blocks of 80 columns (columns of a matrix-product
// chain evolve independently). grid = (2, K), block = 256 threads.
// Thread tile: 4 rows x 10 cols.
// ---------------------------------------------------------------------------
__global__ __launch_bounds__(256, 1)
void pass1_chunk(const float* __restrict__ A, const float* __restrict__ inp,
                 const float* __restrict__ Bst)
{
    extern __shared__ float sm[];
    float* As = sm;                      // NDIM * APAD
    float* W  = sm + NDIM * APAD;        // 2 * NDIM * 80 (ping-pong)

    const int k   = blockIdx.y;
    const int c0  = blockIdx.x * 80;     // first global augmented column
    const int tid = threadIdx.x;
    const int tx  = tid & 7;             // 8 col-groups of 10
    const int ty  = tid >> 3;            // 32 row-groups of 4
    const int row0 = ty << 2;
    const int q0   = tx * 10;

    // init: P columns = identity columns, Y columns = 0
    for (int idx = tid; idx < NDIM * 80; idx += 256) {
        int i = idx / 80;
        int c = idx - i * 80;
        W[idx] = (c0 + c == i) ? 1.0f : 0.0f;
    }

    int cur = 0;
    for (int lt = 0; lt < CSZ; ++lt) {
        const int t = k * CSZ + lt;
        __syncthreads();
        // stage A_t (row-major, padded) — coalesced float4 loads
        const float4* Ag = reinterpret_cast<const float4*>(A + (size_t)t * (NDIM * NDIM));
#pragma unroll
        for (int v = 0; v < 16; ++v) {
            int e = tid + v * 256;            // 0..4095 float4s
            float4 val = Ag[e];
            int r  = e >> 5;
            int c4 = (e & 31) << 2;
            float* dst = As + r * APAD + c4;  // 16B-aligned (528*r + 4*c4 bytes)
            dst[0] = val.x; dst[1] = val.y; dst[2] = val.z; dst[3] = val.w;
        }
        __syncthreads();

        float acc[4][10];
#pragma unroll
        for (int r = 0; r < 4; ++r)
#pragma unroll
            for (int q = 0; q < 10; ++q) acc[r][q] = 0.0f;

        const float* Wo = W + cur * (NDIM * 80);
#pragma unroll 2
        for (int j = 0; j < NDIM; ++j) {
            float a0 = As[(row0 + 0) * APAD + j];
            float a1 = As[(row0 + 1) * APAD + j];
            float a2 = As[(row0 + 2) * APAD + j];
            float a3 = As[(row0 + 3) * APAD + j];
            const float* wr = Wo + j * 80 + q0;
#pragma unroll
            for (int q = 0; q < 10; ++q) {
                float w = wr[q];
                acc[0][q] += a0 * w;
                acc[1][q] += a1 * w;
                acc[2][q] += a2 * w;
                acc[3][q] += a3 * w;
            }
        }

        // u-injection on augmented columns (global col >= NDIM): y = A y + in*B
        float bv0 = Bst[t * NDIM + row0 + 0];
        float bv1 = Bst[t * NDIM + row0 + 1];
        float bv2 = Bst[t * NDIM + row0 + 2];
        float bv3 = Bst[t * NDIM + row0 + 3];
#pragma unroll
        for (int q = 0; q < 10; ++q) {
            int cg = c0 + q0 + q;
            if (cg >= NDIM) {
                float f = inp[t * BDIM + (cg - NDIM)];
                acc[0][q] += f * bv0;
                acc[1][q] += f * bv1;
                acc[2][q] += f * bv2;
                acc[3][q] += f * bv3;
            }
        }

        float* Wn = W + (1 - cur) * (NDIM * 80);
#pragma unroll
        for (int r = 0; r < 4; ++r) {
            float* dst = Wn + (row0 + r) * 80 + q0;
#pragma unroll
            for (int q = 0; q < 10; ++q) dst[q] = acc[r][q];
        }
        cur ^= 1;
    }
    __syncthreads();

    // write out M_k (transposed) and v_k — coalesced over i
    const float* Wf = W + cur * (NDIM * 80);
    for (int idx = tid; idx < NDIM * 80; idx += 256) {
        int c = idx >> 7;          // 0..79 local col
        int i = idx & 127;         // row
        int cg = c0 + c;
        float val = Wf[i * 80 + c];
        if (cg < NDIM) g_Mt[k * (NDIM * NDIM) + cg * NDIM + i] = val;
        else           g_v [k * (BDIM * NDIM) + (cg - NDIM) * NDIM + i] = val;
    }
}

// ---------------------------------------------------------------------------
// Pass 2: sequential scan over chunk transitions; one block per batch column
// (batch columns are fully independent). grid = 32, block = 128 (thread = row i).
// ---------------------------------------------------------------------------
__global__ __launch_bounds__(128, 1)
void pass2_scan(int K)
{
    __shared__ float s[NDIM];
    const int b = blockIdx.x;
    const int i = threadIdx.x;
    s[i] = 0.0f;
    __syncthreads();
    for (int k = 0; k < K; ++k) {
        g_S[k * (BDIM * NDIM) + b * NDIM + i] = s[i];   // state BEFORE chunk k
        const float* M = g_Mt + k * (NDIM * NDIM);       // [j][i] layout (coalesced over i)
        float a0 = 0.f, a1 = 0.f, a2 = 0.f, a3 = 0.f;
#pragma unroll 4
        for (int j = 0; j < NDIM; j += 4) {
            a0 += M[(j + 0) * NDIM + i] * s[j + 0];
            a1 += M[(j + 1) * NDIM + i] * s[j + 1];
            a2 += M[(j + 2) * NDIM + i] * s[j + 2];
            a3 += M[(j + 3) * NDIM + i] * s[j + 3];
        }
        float acc = g_v[k * (BDIM * NDIM) + b * NDIM + i] + ((a0 + a1) + (a2 + a3));
        __syncthreads();
        s[i] = acc;
        __syncthreads();
    }
}

// ---------------------------------------------------------------------------
// Pass 3: local re-scan with correct initial state, writes all outputs.
// grid = (2 batch halves of 16 cols, K chunks), block = 128 threads.
// Thread tile: 4 rows x 4 cols.
// ---------------------------------------------------------------------------
__global__ __launch_bounds__(128, 1)
void pass3_rescan(const float* __restrict__ A, const float* __restrict__ inp,
                  const float* __restrict__ Bst, float* __restrict__ out)
{
    extern __shared__ float sm[];
    float* As = sm;                      // NDIM * APAD
    float* X  = sm + NDIM * APAD;        // 2 * NDIM * 16 (ping-pong)

    const int k   = blockIdx.y;
    const int b0  = blockIdx.x * 16;
    const int tid = threadIdx.x;
    const int tx  = tid & 3;             // 4 col-groups of 4
    const int ty  = tid >> 2;            // 32 row-groups of 4
    const int row0 = ty << 2;
    const int q0   = tx << 2;

    // init X from chunk-start state
    for (int idx = tid; idx < NDIM * 16; idx += 128) {
        int c = idx >> 7;
        int i = idx & 127;
        X[i * 16 + c] = g_S[k * (BDIM * NDIM) + (b0 + c) * NDIM + i];
    }

    int cur = 0;
    for (int lt = 0; lt < CSZ; ++lt) {
        const int t = k * CSZ + lt;
        __syncthreads();
        const float4* Ag = reinterpret_cast<const float4*>(A + (size_t)t * (NDIM * NDIM));
#pragma unroll
        for (int v = 0; v < 32; ++v) {
            int e = tid + v * 128;
            float4 val = Ag[e];
            int r  = e >> 5;
            int c4 = (e & 31) << 2;
            float* dst = As + r * APAD + c4;
            dst[0] = val.x; dst[1] = val.y; dst[2] = val.z; dst[3] = val.w;
        }
        __syncthreads();

        float acc[4][4];
#pragma unroll
        for (int r = 0; r < 4; ++r)
#pragma unroll
            for (int q = 0; q < 4; ++q) acc[r][q] = 0.0f;

        const float* Xo = X + cur * (NDIM * 16);
#pragma unroll 2
        for (int j = 0; j < NDIM; ++j) {
            float a0 = As[(row0 + 0) * APAD + j];
            float a1 = As[(row0 + 1) * APAD + j];
            float a2 = As[(row0 + 2) * APAD + j];
            float a3 = As[(row0 + 3) * APAD + j];
            const float* xr = Xo + j * 16 + q0;
#pragma unroll
            for (int q = 0; q < 4; ++q) {
                float w = xr[q];
                acc[0][q] += a0 * w;
                acc[1][q] += a1 * w;
                acc[2][q] += a2 * w;
                acc[3][q] += a3 * w;
            }
        }

        float bv0 = Bst[t * NDIM + row0 + 0];
        float bv1 = Bst[t * NDIM + row0 + 1];
        float bv2 = Bst[t * NDIM + row0 + 2];
        float bv3 = Bst[t * NDIM + row0 + 3];

        float* Xn = X + (1 - cur) * (NDIM * 16);
#pragma unroll
        for (int q = 0; q < 4; ++q) {
            int b = b0 + q0 + q;
            float f = inp[t * BDIM + b];
            float v0 = acc[0][q] + f * bv0;
            float v1 = acc[1][q] + f * bv1;
            float v2 = acc[2][q] + f * bv2;
            float v3 = acc[3][q] + f * bv3;
            Xn[(row0 + 0) * 16 + q0 + q] = v0;
            Xn[(row0 + 1) * 16 + q0 + q] = v1;
            Xn[(row0 + 2) * 16 + q0 + q] = v2;
            Xn[(row0 + 3) * 16 + q0 + q] = v3;
            // out[t][b][i], 4 consecutive i — aligned float4 store
            float4* op = reinterpret_cast<float4*>(out + (size_t)t * (BDIM * NDIM)
                                                       + (size_t)b * NDIM + row0);
            *op = make_float4(v0, v1, v2, v3);
        }
        cur ^= 1;
    }
}

// ---------------------------------------------------------------------------
extern "C" void kernel_launch(void* const* d_in, const int* in_sizes, int n_in,
                              void* d_out, int out_size)
{
    // identify inputs by element count (A is the largest; inputs = L*32; B = L*128)
    int ia = 0;
    for (int i = 1; i < n_in; ++i)
        if (in_sizes[i] > in_sizes[ia]) ia = i;
    const float* A = (const float*)d_in[ia];
    const int L = in_sizes[ia] / (NDIM * NDIM);
    const float* inp = nullptr;
    const float* Bst = nullptr;
    for (int i = 0; i < n_in; ++i) {
        if (i == ia) continue;
        if (in_sizes[i] == L * BDIM) inp = (const float*)d_in[i];
        else                         Bst = (const float*)d_in[i];
    }
    float* out = (float*)d_out;
    const int K = L / CSZ;   // 64 for L=1024

    const int smem1 = (NDIM * APAD + 2 * NDIM * 80) * (int)sizeof(float);  // ~146 KB
    const int smem3 = (NDIM * APAD + 2 * NDIM * 16) * (int)sizeof(float);  // ~82 KB
    cudaFuncSetAttribute(pass1_chunk,  cudaFuncAttributeMaxDynamicSharedMemorySize, smem1);
    cudaFuncSetAttribute(pass3_rescan, cudaFuncAttributeMaxDynamicSharedMemorySize, smem3);

    pass1_chunk <<<dim3(2, K), 256, smem1>>>(A, inp, Bst);
    pass2_scan  <<<BDIM, NDIM>>>(K);
    pass3_rescan<<<dim3(2, K), 128, smem3>>>(A, inp, Bst, out);
}

// round 8
// speedup vs baseline: 1.2893x; 1.2893x over previous
#include <cuda_runtime.h>

// HiPPO-LegS scan:  x_t = A_t x_{t-1} + inputs[t,b] * B_t,  x_{-1} = 0
//   inputs    : (L, 32)      float32
//   A_stacked : (L, 128,128) float32
//   B_stacked : (L, 128)     float32
//   out       : (L, 32, 128) float32
//
// Chunked parallel scan, C = 16, K = L/C:
//   Pass 1: per chunk, run the augmented chain [P | y] <- A_t [P | y] (+u_t).
//           Every step, store P_t (transposed) to g_P and y_t to out.
//   Pass 2: sequential scan over K chunk transitions (M_k = P at chunk end,
//           v_k = y at chunk end read from out), writes chunk-start states g_S.
//   Pass 3: out[t] += P_t * S_k   (fully parallel over t).

#define NDIM 128
#define BDIM 32
#define CSZ  16
#define KMAX 64
#define LMAX 1024
#define APAD 132   // padded A-tile row stride (floats)

// scratch (__device__ globals only — no allocations allowed)
__device__ float g_P[(size_t)LMAX * NDIM * NDIM];   // [t][j][i] = P_t[i][j]  (64 MB)
__device__ float g_S[KMAX * BDIM * NDIM];           // [k][b][i] state BEFORE chunk k

// ---------------------------------------------------------------------------
// Pass 1: chunk reduction. Augmented state W = [P (128 cols) | Y (32 cols)],
// 160 columns split across 2 blocks of 80. grid = (2, K), block = 256.
// Thread tile: 4 rows x 10 cols. Per step, stores its slice of P_t / y_t.
// ---------------------------------------------------------------------------
__global__ __launch_bounds__(256, 1)
void pass1_chunk(const float* __restrict__ A, const float* __restrict__ inp,
                 const float* __restrict__ Bst, float* __restrict__ outp)
{
    extern __shared__ float sm[];
    float* As = sm;                      // NDIM * APAD
    float* W  = sm + NDIM * APAD;        // 2 * NDIM * 80 (ping-pong)

    const int k   = blockIdx.y;
    const int c0  = blockIdx.x * 80;     // first global augmented column
    const int tid = threadIdx.x;
    const int tx  = tid & 7;             // 8 col-groups of 10
    const int ty  = tid >> 3;            // 32 row-groups of 4
    const int row0 = ty << 2;
    const int q0   = tx * 10;

    // init: P columns = identity columns, Y columns = 0
    for (int idx = tid; idx < NDIM * 80; idx += 256) {
        int i = idx / 80;
        int c = idx - i * 80;
        W[idx] = (c0 + c == i) ? 1.0f : 0.0f;
    }

    int cur = 0;
    for (int lt = 0; lt < CSZ; ++lt) {
        const int t = k * CSZ + lt;
        __syncthreads();
        // stage A_t (row-major, padded) — coalesced float4 loads
        const float4* Ag = reinterpret_cast<const float4*>(A + (size_t)t * (NDIM * NDIM));
#pragma unroll
        for (int v = 0; v < 16; ++v) {
            int e = tid + v * 256;
            float4 val = Ag[e];
            int r  = e >> 5;
            int c4 = (e & 31) << 2;
            float* dst = As + r * APAD + c4;
            dst[0] = val.x; dst[1] = val.y; dst[2] = val.z; dst[3] = val.w;
        }
        __syncthreads();

        float acc[4][10];
#pragma unroll
        for (int r = 0; r < 4; ++r)
#pragma unroll
            for (int q = 0; q < 10; ++q) acc[r][q] = 0.0f;

        const float* Wo = W + cur * (NDIM * 80);
#pragma unroll 2
        for (int j = 0; j < NDIM; ++j) {
            float a0 = As[(row0 + 0) * APAD + j];
            float a1 = As[(row0 + 1) * APAD + j];
            float a2 = As[(row0 + 2) * APAD + j];
            float a3 = As[(row0 + 3) * APAD + j];
            const float* wr = Wo + j * 80 + q0;
#pragma unroll
            for (int q = 0; q < 10; ++q) {
                float w = wr[q];
                acc[0][q] += a0 * w;
                acc[1][q] += a1 * w;
                acc[2][q] += a2 * w;
                acc[3][q] += a3 * w;
            }
        }

        // u-injection on augmented columns (global col >= NDIM): y = A y + in*B
        float bv0 = Bst[t * NDIM + row0 + 0];
        float bv1 = Bst[t * NDIM + row0 + 1];
        float bv2 = Bst[t * NDIM + row0 + 2];
        float bv3 = Bst[t * NDIM + row0 + 3];
#pragma unroll
        for (int q = 0; q < 10; ++q) {
            int cg = c0 + q0 + q;
            if (cg >= NDIM) {
                float f = inp[t * BDIM + (cg - NDIM)];
                acc[0][q] += f * bv0;
                acc[1][q] += f * bv1;
                acc[2][q] += f * bv2;
                acc[3][q] += f * bv3;
            }
        }

        // per-step global stores straight from registers:
        //   P columns -> g_P[t][cg][i]   (transposed layout, float4 over i)
        //   Y columns -> out[t][b][i]
#pragma unroll
        for (int q = 0; q < 10; ++q) {
            int cg = c0 + q0 + q;
            float4 v4 = make_float4(acc[0][q], acc[1][q], acc[2][q], acc[3][q]);
            if (cg < NDIM)
                *reinterpret_cast<float4*>(g_P + ((size_t)t * NDIM + cg) * NDIM + row0) = v4;
            else
                *reinterpret_cast<float4*>(outp + (size_t)t * (BDIM * NDIM)
                                                + (cg - NDIM) * NDIM + row0) = v4;
        }

        float* Wn = W + (1 - cur) * (NDIM * 80);
#pragma unroll
        for (int r = 0; r < 4; ++r) {
            float* dst = Wn + (row0 + r) * 80 + q0;
#pragma unroll
            for (int q = 0; q < 10; ++q) dst[q] = acc[r][q];
        }
        cur ^= 1;
    }
}

// ---------------------------------------------------------------------------
// Pass 2: sequential scan over chunk transitions; one block per batch column.
// grid = 32, block = 512. Thread (i0 = (tid&31)*4, q = tid>>5) covers a
// float4 of rows and a j-slice of 8; smem tree-reduce over the 16 j-slices.
// M_k = g_P at chunk end; v_k = out at chunk end (pass3 hasn't run yet).
// ---------------------------------------------------------------------------
__global__ __launch_bounds__(512, 1)
void pass2_scan(const float* __restrict__ outy, int K)
{
    __shared__ float s[NDIM];
    __shared__ float part[16 * NDIM];
    const int b   = blockIdx.x;
    const int tid = threadIdx.x;
    const int i0  = (tid & 31) << 2;
    const int q   = tid >> 5;            // 0..15
    const int j0  = q << 3;

    if (tid < NDIM) s[tid] = 0.0f;
    __syncthreads();

    for (int k = 0; k < K; ++k) {
        if (tid < NDIM)
            g_S[k * (BDIM * NDIM) + b * NDIM + tid] = s[tid];  // state BEFORE chunk k

        const float* M = g_P + ((size_t)(k * CSZ + CSZ - 1)) * (NDIM * NDIM);
        float4 acc = make_float4(0.f, 0.f, 0.f, 0.f);
#pragma unroll
        for (int jj = 0; jj < 8; ++jj) {
            int j = j0 + jj;
            float sj = s[j];                                     // uniform -> broadcast
            float4 m = *reinterpret_cast<const float4*>(M + j * NDIM + i0);
            acc.x += m.x * sj; acc.y += m.y * sj;
            acc.z += m.z * sj; acc.w += m.w * sj;
        }
        *reinterpret_cast<float4*>(&part[q * NDIM + i0]) = acc;
        __syncthreads();

        if (tid < NDIM) {
            float r = outy[((size_t)(k * CSZ + CSZ - 1)) * (BDIM * NDIM) + b * NDIM + tid];
#pragma unroll
            for (int qq = 0; qq < 16; ++qq) r += part[qq * NDIM + tid];
            s[tid] = r;
        }
        __syncthreads();
    }
}

// ---------------------------------------------------------------------------
// Pass 3: out[t][b][i] += sum_j P_t[i][j] * S_k[b][j].  grid = L, block = 256.
// Thread: i = tid&127, batch half of 16. S staged in smem padded [j][b].
// ---------------------------------------------------------------------------
__global__ __launch_bounds__(256, 1)
void pass3_apply(float* __restrict__ outp)
{
    __shared__ float sS[NDIM * 36];      // [j*36 + b], 16B-aligned float4 rows
    const int t   = blockIdx.x;
    const int k   = t >> 4;              // CSZ = 16
    const int tid = threadIdx.x;

    for (int idx = tid; idx < NDIM * BDIM; idx += 256) {
        int b = idx >> 7, j = idx & 127;
        sS[j * 36 + b] = g_S[k * (BDIM * NDIM) + idx];
    }
    __syncthreads();

    const int i  = tid & 127;
    const int b0 = (tid >> 7) << 4;      // 0 or 16
    const size_t obase = (size_t)t * (BDIM * NDIM);

    float acc[16];
#pragma unroll
    for (int bb = 0; bb < 16; ++bb)
        acc[bb] = outp[obase + (b0 + bb) * NDIM + i];   // y_t (written by pass1)

    const float* P = g_P + (size_t)t * (NDIM * NDIM);
#pragma unroll 4
    for (int j = 0; j < NDIM; ++j) {
        float p = P[j * NDIM + i];                       // coalesced over i
        float4 s0 = *reinterpret_cast<const float4*>(&sS[j * 36 + b0 + 0]);
        float4 s1 = *reinterpret_cast<const float4*>(&sS[j * 36 + b0 + 4]);
        float4 s2 = *reinterpret_cast<const float4*>(&sS[j * 36 + b0 + 8]);
        float4 s3 = *reinterpret_cast<const float4*>(&sS[j * 36 + b0 + 12]);
        acc[0]  += p * s0.x; acc[1]  += p * s0.y; acc[2]  += p * s0.z; acc[3]  += p * s0.w;
        acc[4]  += p * s1.x; acc[5]  += p * s1.y; acc[6]  += p * s1.z; acc[7]  += p * s1.w;
        acc[8]  += p * s2.x; acc[9]  += p * s2.y; acc[10] += p * s2.z; acc[11] += p * s2.w;
        acc[12] += p * s3.x; acc[13] += p * s3.y; acc[14] += p * s3.z; acc[15] += p * s3.w;
    }

#pragma unroll
    for (int bb = 0; bb < 16; ++bb)
        outp[obase + (b0 + bb) * NDIM + i] = acc[bb];
}

// ---------------------------------------------------------------------------
extern "C" void kernel_launch(void* const* d_in, const int* in_sizes, int n_in,
                              void* d_out, int out_size)
{
    // identify inputs by element count (A is the largest; inputs = L*32; B = L*128)
    int ia = 0;
    for (int i = 1; i < n_in; ++i)
        if (in_sizes[i] > in_sizes[ia]) ia = i;
    const float* A = (const float*)d_in[ia];
    const int L = in_sizes[ia] / (NDIM * NDIM);
    const float* inp = nullptr;
    const float* Bst = nullptr;
    for (int i = 0; i < n_in; ++i) {
        if (i == ia) continue;
        if (in_sizes[i] == L * BDIM) inp = (const float*)d_in[i];
        else                         Bst = (const float*)d_in[i];
    }
    float* out = (float*)d_out;
    const int K = L / CSZ;   // 64 for L=1024

    const int smem1 = (NDIM * APAD + 2 * NDIM * 80) * (int)sizeof(float);  // ~147 KB
    cudaFuncSetAttribute(pass1_chunk, cudaFuncAttributeMaxDynamicSharedMemorySize, smem1);

    pass1_chunk<<<dim3(2, K), 256, smem1>>>(A, inp, Bst, out);
    pass2_scan <<<BDIM, 512>>>(out, K);
    pass3_apply<<<L, 256>>>(out);
}